// round 8
// baseline (speedup 1.0000x reference)
#include <cuda_runtime.h>

// ---------------- device scratch (no allocation allowed) --------------------
__device__ float    g_pre[(size_t)2 * 16384 * 1024]; // x@Wih.T per dir
__device__ float    g_h[2][2][8192];                 // [dir][buf][j*32+b]
__device__ float    g_c[2][8192];
__device__ float    g_dh0[2][8192];
__device__ float    g_dh1[2][8192];
__device__ float    g_part[(size_t)64 * 256 * 96];   // y partials
__device__ unsigned g_ctr_enc[1024];
__device__ unsigned g_ctr_dec[128];

// ------------------------------ helpers -------------------------------------
__device__ __forceinline__ unsigned long long pk2(float lo, float hi) {
    unsigned long long r; asm("mov.b64 %0,{%1,%2};" : "=l"(r) : "f"(lo), "f"(hi)); return r;
}
__device__ __forceinline__ void ffma2(unsigned long long& d, unsigned long long a,
                                      unsigned long long b) {
    asm("fma.rn.f32x2 %0,%1,%2,%0;" : "+l"(d) : "l"(a), "l"(b));
}
__device__ __forceinline__ float2 upk2(unsigned long long v) {
    float lo, hi; asm("mov.b64 {%0,%1},%2;" : "=f"(lo), "=f"(hi) : "l"(v));
    return make_float2(lo, hi);
}
__device__ __forceinline__ float sigf(float x) { return 1.f / (1.f + __expf(-x)); }

// one-shot grid barrier (counter pre-zeroed, used exactly once)
__device__ __forceinline__ void grid_barrier(unsigned* ctr, unsigned n) {
    __syncthreads();
    __threadfence();
    if (threadIdx.x == 0) {
        if (atomicAdd(ctr, 1u) + 1u < n)
            while (*((volatile unsigned*)ctr) < n) __nanosleep(32);
    }
    __syncthreads();
}

__global__ void init_kernel() {
    int i = threadIdx.x;
    if (i < 1024) g_ctr_enc[i] = 0u;
    if (i < 128)  g_ctr_dec[i] = 0u;
}

// ---------------------------------------------------------------------------
// gemm_pre: 128x128x16 tile, 256 thr, 8x8 microtile, FFMA2 along n.
// ---------------------------------------------------------------------------
__global__ void __launch_bounds__(256) gemm_pre(const float* __restrict__ X,
                                                const float* __restrict__ Wf,
                                                const float* __restrict__ Wb) {
    __shared__ float As[16 * 132], Bs[16 * 132];
    const int tid = threadIdx.x, dir = blockIdx.z;
    const float* W = dir ? Wb : Wf;
    const int m0 = blockIdx.y << 7, n0 = blockIdx.x << 7;
    const int lrow = tid >> 1, lk = (tid & 1) << 3;
    const int gm = m0 + lrow;
    const int src = dir ? ((511 - (gm >> 5)) * 32 + (gm & 31)) : gm;
    const float* Ar = X + (size_t)src * 1024 + lk;
    const float* Br = W + (size_t)(n0 + lrow) * 1024 + lk;
    const int tm = (tid >> 4) << 3, tn = (tid & 15) << 3;

    unsigned long long acc[8][4];
#pragma unroll
    for (int i = 0; i < 8; i++)
#pragma unroll
        for (int j = 0; j < 4; j++) acc[i][j] = 0ull;

    for (int k0 = 0; k0 < 1024; k0 += 16) {
        float4 a0 = *(const float4*)(Ar + k0), a1 = *(const float4*)(Ar + k0 + 4);
        float4 b0 = *(const float4*)(Br + k0), b1 = *(const float4*)(Br + k0 + 4);
        __syncthreads();
        As[(lk+0)*132+lrow]=a0.x; As[(lk+1)*132+lrow]=a0.y; As[(lk+2)*132+lrow]=a0.z; As[(lk+3)*132+lrow]=a0.w;
        As[(lk+4)*132+lrow]=a1.x; As[(lk+5)*132+lrow]=a1.y; As[(lk+6)*132+lrow]=a1.z; As[(lk+7)*132+lrow]=a1.w;
        Bs[(lk+0)*132+lrow]=b0.x; Bs[(lk+1)*132+lrow]=b0.y; Bs[(lk+2)*132+lrow]=b0.z; Bs[(lk+3)*132+lrow]=b0.w;
        Bs[(lk+4)*132+lrow]=b1.x; Bs[(lk+5)*132+lrow]=b1.y; Bs[(lk+6)*132+lrow]=b1.z; Bs[(lk+7)*132+lrow]=b1.w;
        __syncthreads();
#pragma unroll
        for (int kk = 0; kk < 16; kk++) {
            float4 av0 = *(const float4*)(As + kk*132 + tm);
            float4 av1 = *(const float4*)(As + kk*132 + tm + 4);
            float4 bv0 = *(const float4*)(Bs + kk*132 + tn);
            float4 bv1 = *(const float4*)(Bs + kk*132 + tn + 4);
            unsigned long long bp0 = pk2(bv0.x, bv0.y), bp1 = pk2(bv0.z, bv0.w);
            unsigned long long bp2 = pk2(bv1.x, bv1.y), bp3 = pk2(bv1.z, bv1.w);
            float am[8] = {av0.x, av0.y, av0.z, av0.w, av1.x, av1.y, av1.z, av1.w};
#pragma unroll
            for (int mr = 0; mr < 8; mr++) {
                unsigned long long ap = pk2(am[mr], am[mr]);
                ffma2(acc[mr][0], ap, bp0); ffma2(acc[mr][1], ap, bp1);
                ffma2(acc[mr][2], ap, bp2); ffma2(acc[mr][3], ap, bp3);
            }
        }
    }
    float* O = g_pre + (size_t)dir * 16777216 + (size_t)(m0 + tm) * 1024 + n0 + tn;
#pragma unroll
    for (int mr = 0; mr < 8; mr++) {
        float2 p0 = upk2(acc[mr][0]), p1 = upk2(acc[mr][1]);
        float2 p2 = upk2(acc[mr][2]), p3 = upk2(acc[mr][3]);
        *(float4*)(O + (size_t)mr * 1024)     = make_float4(p0.x, p0.y, p1.x, p1.y);
        *(float4*)(O + (size_t)mr * 1024 + 4) = make_float4(p2.x, p2.y, p3.x, p3.y);
    }
}

// ---------------------------------------------------------------------------
// Encoder recurrence: grid (64,2). 4 units/CTA, 256 thr.
// phase1 split: bq=tid&3 (8 batches), rgq=(tid>>2)&3 (gate), kc=tid>>4 (k%16).
// ---------------------------------------------------------------------------
#define ENC_SMEM (16*257 + 256*34 + 256*33)

__global__ void __launch_bounds__(256) enc_kernel(const float* __restrict__ WhhF,
                                                  const float* __restrict__ bF,
                                                  const float* __restrict__ WhhB,
                                                  const float* __restrict__ bB) {
    extern __shared__ float sm[];
    float* sm_w = sm;                    // 16*257
    float* sm_h = sm + 4112;             // 256*34
    float* sm_red = sm + 4112 + 8704;    // 256*33

    const int tid = threadIdx.x, dir = blockIdx.y, j0 = blockIdx.x << 2;
    const float* Whh  = dir ? WhhB : WhhF;
    const float* bias = dir ? bB : bF;
    const float* pre  = g_pre + (size_t)dir * 16777216;
    unsigned* ctr = g_ctr_enc + dir * 512;

    for (int idx = tid; idx < 16 * 256; idx += 256) {
        int lr = idx >> 8, k = idx & 255, g = lr >> 2, u = lr & 3;
        sm_w[lr * 257 + k] = Whh[(size_t)(g * 256 + j0 + u) * 256 + k];
    }
    for (int idx = tid; idx < 256 * 34; idx += 256) sm_h[idx] = 0.f;

    const int bq = tid & 3, rgq = (tid >> 2) & 3, kc = tid >> 4;
    const int u2 = tid >> 5, b2 = tid & 31, j2 = j0 + u2;
    float bv4[4] = {0,0,0,0}, cst = 0.f;
    if (tid < 128)
#pragma unroll
        for (int g = 0; g < 4; g++) bv4[g] = bias[g * 256 + j2];
    __syncthreads();

    const unsigned long long* H2 = (const unsigned long long*)sm_h;

    for (int t = 0; t < 512; t++) {
        float p4[4] = {0,0,0,0};
        if (tid < 128) {
            const float* pb = pre + (size_t)(t * 32 + b2) * 1024 + j2;
#pragma unroll
            for (int g = 0; g < 4; g++) p4[g] = __ldg(pb + g * 256);
        }
        unsigned long long acc[4][4];
#pragma unroll
        for (int r = 0; r < 4; r++)
#pragma unroll
            for (int p = 0; p < 4; p++) acc[r][p] = 0ull;
#pragma unroll
        for (int i = 0; i < 16; i++) {
            int k = kc + (i << 4);
            const float* wr = sm_w + k;
            unsigned long long wp0 = pk2(wr[(rgq*4+0)*257], wr[(rgq*4+0)*257]);
            unsigned long long wp1 = pk2(wr[(rgq*4+1)*257], wr[(rgq*4+1)*257]);
            unsigned long long wp2 = pk2(wr[(rgq*4+2)*257], wr[(rgq*4+2)*257]);
            unsigned long long wp3 = pk2(wr[(rgq*4+3)*257], wr[(rgq*4+3)*257]);
            const unsigned long long* hb = H2 + k * 17 + bq * 4;
            unsigned long long h0 = hb[0], h1 = hb[1], h2 = hb[2], h3 = hb[3];
            ffma2(acc[0][0],wp0,h0); ffma2(acc[0][1],wp0,h1); ffma2(acc[0][2],wp0,h2); ffma2(acc[0][3],wp0,h3);
            ffma2(acc[1][0],wp1,h0); ffma2(acc[1][1],wp1,h1); ffma2(acc[1][2],wp1,h2); ffma2(acc[1][3],wp1,h3);
            ffma2(acc[2][0],wp2,h0); ffma2(acc[2][1],wp2,h1); ffma2(acc[2][2],wp2,h2); ffma2(acc[2][3],wp2,h3);
            ffma2(acc[3][0],wp3,h0); ffma2(acc[3][1],wp3,h1); ffma2(acc[3][2],wp3,h2); ffma2(acc[3][3],wp3,h3);
        }
        __syncthreads();
        {
            float* mr_ = sm_red + tid * 33;
#pragma unroll
            for (int r = 0; r < 4; r++)
#pragma unroll
                for (int p = 0; p < 4; p++) {
                    float2 v = upk2(acc[r][p]);
                    mr_[r*8 + p*2] = v.x; mr_[r*8 + p*2 + 1] = v.y;
                }
        }
        __syncthreads();

        if (tid < 128) {
            float s4[4];
#pragma unroll
            for (int g = 0; g < 4; g++) {
                float a = p4[g] + bv4[g];
#pragma unroll
                for (int q = 0; q < 16; q++)
                    a += sm_red[((b2>>3) + g*4 + q*16)*33 + u2*8 + (b2&7)];
                s4[g] = a;
            }
            float iv = sigf(s4[0]), fv = sigf(s4[1]);
            float gv = tanhf(s4[2]), ov = sigf(s4[3]);
            cst = fv * cst + iv * gv;
            g_h[dir][(t + 1) & 1][j2 * 32 + b2] = ov * tanhf(cst);
        }

        grid_barrier(ctr + t, 64);

        const float* src = g_h[dir][(t + 1) & 1];
#pragma unroll 8
        for (int r = 0; r < 32; r++) {
            int idx = r * 256 + tid;
            sm_h[(idx >> 5) * 34 + (idx & 31)] = __ldcg(src + idx);
        }
        __syncthreads();
    }
    if (tid < 128) g_c[dir][j2 * 32 + b2] = cst;
}

// ---------------------------------------------------------------------------
// Decoder: 128 CTAs x 2 units, K=512 ([x|h]), 2 layers x 64 steps.
// ---------------------------------------------------------------------------
#define DEC_SMEM (8*513*2 + 512*34 + 256*17)

__global__ void __launch_bounds__(256) dec_kernel(const float* __restrict__ Wih0,
                                                  const float* __restrict__ Whh0,
                                                  const float* __restrict__ b0,
                                                  const float* __restrict__ Wih1,
                                                  const float* __restrict__ Whh1,
                                                  const float* __restrict__ b1,
                                                  const float* __restrict__ linW) {
    extern __shared__ float sm[];
    float* sm_w0 = sm;                   // 8*513
    float* sm_w1 = sm + 4104;            // 8*513
    float* sm_x  = sm + 8208;            // 512*34
    float* sm_red = sm + 8208 + 17408;   // 256*17

    const int tid = threadIdx.x, cta = blockIdx.x, j0 = cta << 1;

    for (int idx = tid; idx < 8 * 512; idx += 256) {
        int lr = idx >> 9, k = idx & 511, g = lr >> 1, uu = lr & 1;
        size_t grow = (size_t)(g * 256 + j0 + uu) * 256;
        sm_w0[lr * 513 + k] = (k < 256) ? Wih0[grow + k] : Whh0[grow + k - 256];
        sm_w1[lr * 513 + k] = (k < 256) ? Wih1[grow + k] : Whh1[grow + k - 256];
    }

    const int bq = tid & 3, rgq = (tid >> 2) & 3, kc = tid >> 4;
    const int u2 = tid >> 5, b2 = tid & 31, j2 = j0 + u2;
    float b0v[4]={0,0,0,0}, b1v[4]={0,0,0,0}, lwv[3]={0,0,0}, c0=0.f, c1=0.f;
    if (tid < 64) {
#pragma unroll
        for (int g = 0; g < 4; g++) { b0v[g] = b0[g*256+j2]; b1v[g] = b1[g*256+j2]; }
#pragma unroll
        for (int v = 0; v < 3; v++) lwv[v] = linW[v * 256 + j2];
        c0 = __ldcg(&g_c[0][j2 * 32 + b2]);
        c1 = __ldcg(&g_c[1][j2 * 32 + b2]);
    }
    __syncthreads();

    const unsigned long long* X2 = (const unsigned long long*)sm_x;

    for (int t = 0; t < 64; t++) {
        int rb = t & 1, wb = (t + 1) & 1;
        {   // layer0 X = [x(=h1_{t-1}) | h0_{t-1}]
            const float* px = (t == 0) ? (const float*)0 : g_dh1[rb];
            const float* ph = (t == 0) ? g_h[0][0] : g_dh0[rb];
#pragma unroll 8
            for (int r = 0; r < 64; r++) {
                int idx = r * 256 + tid, k = idx >> 5, b = idx & 31;
                float v = (k < 256) ? (px ? __ldcg(px + idx) : 0.f)
                                    : __ldcg(ph + idx - 8192);
                sm_x[k * 34 + b] = v;
            }
        }
        __syncthreads();

        for (int layer = 0; layer < 2; layer++) {
            const float* Wl = layer ? sm_w1 : sm_w0;
            unsigned long long acc[2][4];
#pragma unroll
            for (int r = 0; r < 2; r++)
#pragma unroll
                for (int p = 0; p < 4; p++) acc[r][p] = 0ull;
#pragma unroll 8
            for (int i = 0; i < 32; i++) {
                int k = kc + (i << 4);
                unsigned long long wp0 = pk2(Wl[(rgq*2+0)*513+k], Wl[(rgq*2+0)*513+k]);
                unsigned long long wp1 = pk2(Wl[(rgq*2+1)*513+k], Wl[(rgq*2+1)*513+k]);
                const unsigned long long* hb = X2 + k * 17 + bq * 4;
                unsigned long long h0 = hb[0], h1 = hb[1], h2 = hb[2], h3 = hb[3];
                ffma2(acc[0][0],wp0,h0); ffma2(acc[0][1],wp0,h1);
                ffma2(acc[0][2],wp0,h2); ffma2(acc[0][3],wp0,h3);
                ffma2(acc[1][0],wp1,h0); ffma2(acc[1][1],wp1,h1);
                ffma2(acc[1][2],wp1,h2); ffma2(acc[1][3],wp1,h3);
            }
            __syncthreads();
            {
                float* mr_ = sm_red + tid * 17;
#pragma unroll
                for (int r = 0; r < 2; r++)
#pragma unroll
                    for (int p = 0; p < 4; p++) {
                        float2 v = upk2(acc[r][p]);
                        mr_[r*8 + p*2] = v.x; mr_[r*8 + p*2 + 1] = v.y;
                    }
            }
            __syncthreads();

            if (tid < 64) {
                float s4[4];
#pragma unroll
                for (int g = 0; g < 4; g++) {
                    float a = layer ? b1v[g] : b0v[g];
#pragma unroll
                    for (int q = 0; q < 16; q++)
                        a += sm_red[((b2>>3) + g*4 + q*16)*17 + u2*8 + (b2&7)];
                    s4[g] = a;
                }
                float iv = sigf(s4[0]), fv = sigf(s4[1]);
                float gv = tanhf(s4[2]), ov = sigf(s4[3]);
                if (layer == 0) {
                    c0 = fv * c0 + iv * gv;
                    g_dh0[wb][j2 * 32 + b2] = ov * tanhf(c0);
                } else {
                    c1 = fv * c1 + iv * gv;
                    float h = ov * tanhf(c1);
                    g_dh1[wb][j2 * 32 + b2] = h;
#pragma unroll
                    for (int v = 0; v < 3; v++)
                        g_part[((size_t)t * 256 + (cta*2 + u2)) * 96 + b2*3 + v] = lwv[v] * h;
                }
            }

            grid_barrier(g_ctr_dec + t * 2 + layer, 128);

            if (layer == 0) {   // layer1 X = [h0_t | h1_{t-1}]
                const float* pa  = g_dh0[wb];
                const float* pb2 = (t == 0) ? g_h[1][0] : g_dh1[rb];
#pragma unroll 8
                for (int r = 0; r < 64; r++) {
                    int idx = r * 256 + tid, k = idx >> 5, b = idx & 31;
                    sm_x[k * 34 + b] = (k < 256) ? __ldcg(pa + idx)
                                                 : __ldcg(pb2 + idx - 8192);
                }
                __syncthreads();
            }
        }
    }
}

__global__ void reduce_y(const float* __restrict__ lin_b, float* __restrict__ out) {
    int t = blockIdx.x, o = threadIdx.x;   // o = b*3+v, 96 threads
    const float* p = g_part + (size_t)t * 256 * 96 + o;
    float a0 = 0.f, a1 = 0.f, a2 = 0.f, a3 = 0.f;
#pragma unroll 4
    for (int s = 0; s < 256; s += 4) {
        a0 += p[(size_t)(s + 0) * 96]; a1 += p[(size_t)(s + 1) * 96];
        a2 += p[(size_t)(s + 2) * 96]; a3 += p[(size_t)(s + 3) * 96];
    }
    out[t * 96 + o] = lin_b[o % 3] + ((a0 + a1) + (a2 + a3));
}

// ---------------------------------------------------------------------------
extern "C" void kernel_launch(void* const* d_in, const int* in_sizes, int n_in,
                              void* d_out, int out_size) {
    (void)in_sizes; (void)n_in; (void)out_size;
    const float* X     = (const float*)d_in[0];
    const float* eWihF = (const float*)d_in[1];
    const float* eWhhF = (const float*)d_in[2];
    const float* ebF   = (const float*)d_in[3];
    const float* eWihB = (const float*)d_in[4];
    const float* eWhhB = (const float*)d_in[5];
    const float* ebB   = (const float*)d_in[6];
    const float* dWih0 = (const float*)d_in[7];
    const float* dWhh0 = (const float*)d_in[8];
    const float* db0   = (const float*)d_in[9];
    const float* dWih1 = (const float*)d_in[10];
    const float* dWhh1 = (const float*)d_in[11];
    const float* db1   = (const float*)d_in[12];
    const float* linW  = (const float*)d_in[13];
    const float* linb  = (const float*)d_in[14];
    float* out = (float*)d_out;

    cudaFuncSetAttribute(enc_kernel, cudaFuncAttributeMaxDynamicSharedMemorySize,
                         ENC_SMEM * 4);
    cudaFuncSetAttribute(dec_kernel, cudaFuncAttributeMaxDynamicSharedMemorySize,
                         DEC_SMEM * 4);

    init_kernel<<<1, 1024>>>();
    gemm_pre<<<dim3(8, 128, 2), 256>>>(X, eWihF, eWihB);
    enc_kernel<<<dim3(64, 2), 256, ENC_SMEM * 4>>>(eWhhF, ebF, eWhhB, ebB);
    dec_kernel<<<128, 256, DEC_SMEM * 4>>>(dWih0, dWhh0, db0, dWih1, dWhh1, db1, linW);
    reduce_y<<<64, 96>>>(linb, out);
}

// round 17
// speedup vs baseline: 1.2360x; 1.2360x over previous
#include <cuda_runtime.h>

typedef unsigned long long ull;

// ---------------- device scratch (no allocation allowed) --------------------
__device__ float    g_pre[(size_t)2 * 16384 * 1024]; // x@Wih.T per dir
__device__ float    g_h[2][2][8192];                 // [dir][buf][j*32+b]
__device__ float    g_c[2][8192];
__device__ float    g_dh0[8192];                     // decoder layer0 h
__device__ float    g_dh1[8192];                     // decoder layer1 h
__device__ float    g_part[(size_t)64 * 256 * 96];   // y partials
__device__ unsigned g_ctr_enc[1024];
__device__ unsigned g_ctr_dec[128];

// ------------------------------ helpers -------------------------------------
__device__ __forceinline__ ull pk2(float lo, float hi) {
    ull r; asm("mov.b64 %0,{%1,%2};" : "=l"(r) : "f"(lo), "f"(hi)); return r;
}
__device__ __forceinline__ void ffma2(ull& d, ull a, ull b) {
    asm("fma.rn.f32x2 %0,%1,%2,%0;" : "+l"(d) : "l"(a), "l"(b));
}
__device__ __forceinline__ float2 upk2(ull v) {
    float lo, hi; asm("mov.b64 {%0,%1},%2;" : "=f"(lo), "=f"(hi) : "l"(v));
    return make_float2(lo, hi);
}
__device__ __forceinline__ float sigf(float x) { return 1.f / (1.f + __expf(-x)); }

// one-shot grid barrier: release-red arrival + acquire hot-poll (no membar)
__device__ __forceinline__ void barrier_sync(unsigned* ctr, unsigned n) {
    __syncthreads();
    if (threadIdx.x == 0) {
        unsigned one = 1u;
        asm volatile("red.release.gpu.global.add.u32 [%0], %1;"
                     :: "l"(ctr), "r"(one) : "memory");
        unsigned v;
        do {
            asm volatile("ld.acquire.gpu.global.u32 %0, [%1];"
                         : "=r"(v) : "l"(ctr) : "memory");
        } while (v < n);
    }
    __syncthreads();
}

__global__ void init_kernel() {
    int i = threadIdx.x;
    if (i < 1024) g_ctr_enc[i] = 0u;
    if (i < 128)  g_ctr_dec[i] = 0u;
}

// ---------------------------------------------------------------------------
// gemm_pre: 128x128x16 tile, 256 thr, 8x8 microtile, FFMA2 along n.
// ---------------------------------------------------------------------------
__global__ void __launch_bounds__(256, 2) gemm_pre(const float* __restrict__ X,
                                                   const float* __restrict__ Wf,
                                                   const float* __restrict__ Wb) {
    __shared__ float As[16 * 132], Bs[16 * 132];
    const int tid = threadIdx.x, dir = blockIdx.z;
    const float* W = dir ? Wb : Wf;
    const int m0 = blockIdx.y << 7, n0 = blockIdx.x << 7;
    const int lrow = tid >> 1, lk = (tid & 1) << 3;
    const int gm = m0 + lrow;
    const int src = dir ? ((511 - (gm >> 5)) * 32 + (gm & 31)) : gm;
    const float* Ar = X + (size_t)src * 1024 + lk;
    const float* Br = W + (size_t)(n0 + lrow) * 1024 + lk;
    const int tm = (tid >> 4) << 3, tn = (tid & 15) << 3;

    ull acc[8][4];
#pragma unroll
    for (int i = 0; i < 8; i++)
#pragma unroll
        for (int j = 0; j < 4; j++) acc[i][j] = 0ull;

    for (int k0 = 0; k0 < 1024; k0 += 16) {
        float4 a0 = *(const float4*)(Ar + k0), a1 = *(const float4*)(Ar + k0 + 4);
        float4 b0 = *(const float4*)(Br + k0), b1 = *(const float4*)(Br + k0 + 4);
        __syncthreads();
        As[(lk+0)*132+lrow]=a0.x; As[(lk+1)*132+lrow]=a0.y; As[(lk+2)*132+lrow]=a0.z; As[(lk+3)*132+lrow]=a0.w;
        As[(lk+4)*132+lrow]=a1.x; As[(lk+5)*132+lrow]=a1.y; As[(lk+6)*132+lrow]=a1.z; As[(lk+7)*132+lrow]=a1.w;
        Bs[(lk+0)*132+lrow]=b0.x; Bs[(lk+1)*132+lrow]=b0.y; Bs[(lk+2)*132+lrow]=b0.z; Bs[(lk+3)*132+lrow]=b0.w;
        Bs[(lk+4)*132+lrow]=b1.x; Bs[(lk+5)*132+lrow]=b1.y; Bs[(lk+6)*132+lrow]=b1.z; Bs[(lk+7)*132+lrow]=b1.w;
        __syncthreads();
#pragma unroll
        for (int kk = 0; kk < 16; kk++) {
            float4 av0 = *(const float4*)(As + kk*132 + tm);
            float4 av1 = *(const float4*)(As + kk*132 + tm + 4);
            float4 bv0 = *(const float4*)(Bs + kk*132 + tn);
            float4 bv1 = *(const float4*)(Bs + kk*132 + tn + 4);
            ull bp0 = pk2(bv0.x, bv0.y), bp1 = pk2(bv0.z, bv0.w);
            ull bp2 = pk2(bv1.x, bv1.y), bp3 = pk2(bv1.z, bv1.w);
            float am[8] = {av0.x, av0.y, av0.z, av0.w, av1.x, av1.y, av1.z, av1.w};
#pragma unroll
            for (int mr = 0; mr < 8; mr++) {
                ull ap = pk2(am[mr], am[mr]);
                ffma2(acc[mr][0], ap, bp0); ffma2(acc[mr][1], ap, bp1);
                ffma2(acc[mr][2], ap, bp2); ffma2(acc[mr][3], ap, bp3);
            }
        }
    }
    float* O = g_pre + (size_t)dir * 16777216 + (size_t)(m0 + tm) * 1024 + n0 + tn;
#pragma unroll
    for (int mr = 0; mr < 8; mr++) {
        float2 p0 = upk2(acc[mr][0]), p1 = upk2(acc[mr][1]);
        float2 p2 = upk2(acc[mr][2]), p3 = upk2(acc[mr][3]);
        *(float4*)(O + (size_t)mr * 1024)     = make_float4(p0.x, p0.y, p1.x, p1.y);
        *(float4*)(O + (size_t)mr * 1024 + 4) = make_float4(p2.x, p2.y, p3.x, p3.y);
    }
}

// ---------------------------------------------------------------------------
// Encoder recurrence: grid (64,2). 4 units/CTA, 256 thr.
// phase1 split: bq=tid&3 (8 batches), rgq=(tid>>2)&3 (gate), kc=tid>>4 (k%16).
// ---------------------------------------------------------------------------
#define ENC_SMEM (16*257 + 256*34 + 256*33)

__global__ void __launch_bounds__(256) enc_kernel(const float* __restrict__ WhhF,
                                                  const float* __restrict__ bF,
                                                  const float* __restrict__ WhhB,
                                                  const float* __restrict__ bB) {
    extern __shared__ float sm[];
    float* sm_w = sm;                    // 16*257
    float* sm_h = sm + 4112;             // 256*34 (8-byte aligned)
    float* sm_red = sm + 4112 + 8704;    // 256*33

    const int tid = threadIdx.x, dir = blockIdx.y, j0 = blockIdx.x << 2;
    const float* Whh  = dir ? WhhB : WhhF;
    const float* bias = dir ? bB : bF;
    const float* pre  = g_pre + (size_t)dir * 16777216;
    unsigned* ctr = g_ctr_enc + dir * 512;

    for (int idx = tid; idx < 16 * 256; idx += 256) {
        int lr = idx >> 8, k = idx & 255, g = lr >> 2, u = lr & 3;
        sm_w[lr * 257 + k] = Whh[(size_t)(g * 256 + j0 + u) * 256 + k];
    }
    for (int idx = tid; idx < 256 * 34; idx += 256) sm_h[idx] = 0.f;

    const int bq = tid & 3, rgq = (tid >> 2) & 3, kc = tid >> 4;
    const int u2 = tid >> 5, b2 = tid & 31, j2 = j0 + u2;
    float bv4[4] = {0,0,0,0}, cst = 0.f;
    if (tid < 128)
#pragma unroll
        for (int g = 0; g < 4; g++) bv4[g] = bias[g * 256 + j2];
    __syncthreads();

    const ull* H2 = (const ull*)sm_h;
    ull* H2w = (ull*)sm_h;

    for (int t = 0; t < 512; t++) {
        float p4[4] = {0,0,0,0};
        if (tid < 128) {
            const float* pb = pre + (size_t)(t * 32 + b2) * 1024 + j2;
#pragma unroll
            for (int g = 0; g < 4; g++) p4[g] = __ldg(pb + g * 256);
        }
        ull acc[4][4];
#pragma unroll
        for (int r = 0; r < 4; r++)
#pragma unroll
            for (int p = 0; p < 4; p++) acc[r][p] = 0ull;
#pragma unroll
        for (int i = 0; i < 16; i++) {
            int k = kc + (i << 4);
            const float* wr = sm_w + k;
            ull wp0 = pk2(wr[(rgq*4+0)*257], wr[(rgq*4+0)*257]);
            ull wp1 = pk2(wr[(rgq*4+1)*257], wr[(rgq*4+1)*257]);
            ull wp2 = pk2(wr[(rgq*4+2)*257], wr[(rgq*4+2)*257]);
            ull wp3 = pk2(wr[(rgq*4+3)*257], wr[(rgq*4+3)*257]);
            const ull* hb = H2 + k * 17 + bq * 4;
            ull h0 = hb[0], h1 = hb[1], h2 = hb[2], h3 = hb[3];
            ffma2(acc[0][0],wp0,h0); ffma2(acc[0][1],wp0,h1); ffma2(acc[0][2],wp0,h2); ffma2(acc[0][3],wp0,h3);
            ffma2(acc[1][0],wp1,h0); ffma2(acc[1][1],wp1,h1); ffma2(acc[1][2],wp1,h2); ffma2(acc[1][3],wp1,h3);
            ffma2(acc[2][0],wp2,h0); ffma2(acc[2][1],wp2,h1); ffma2(acc[2][2],wp2,h2); ffma2(acc[2][3],wp2,h3);
            ffma2(acc[3][0],wp3,h0); ffma2(acc[3][1],wp3,h1); ffma2(acc[3][2],wp3,h2); ffma2(acc[3][3],wp3,h3);
        }
        __syncthreads();
        {
            float* mr_ = sm_red + tid * 33;
#pragma unroll
            for (int r = 0; r < 4; r++)
#pragma unroll
                for (int p = 0; p < 4; p++) {
                    float2 v = upk2(acc[r][p]);
                    mr_[r*8 + p*2] = v.x; mr_[r*8 + p*2 + 1] = v.y;
                }
        }
        __syncthreads();

        if (tid < 128) {
            float s4[4];
#pragma unroll
            for (int g = 0; g < 4; g++) {
                float a = p4[g] + bv4[g];
#pragma unroll
                for (int q = 0; q < 16; q++)
                    a += sm_red[((b2>>3) + g*4 + q*16)*33 + u2*8 + (b2&7)];
                s4[g] = a;
            }
            float iv = sigf(s4[0]), fv = sigf(s4[1]);
            float gv = tanhf(s4[2]), ov = sigf(s4[3]);
            cst = fv * cst + iv * gv;
            g_h[dir][(t + 1) & 1][j2 * 32 + b2] = ov * tanhf(cst);
        }

        barrier_sync(ctr + t, 64);

        // restage full h_t as 64-bit loads (16 per thread)
        const ull* src = (const ull*)g_h[dir][(t + 1) & 1];
#pragma unroll
        for (int r = 0; r < 16; r++) {
            int i2 = r * 256 + tid;                 // ull index 0..4095
            H2w[(i2 >> 4) * 17 + (i2 & 15)] = __ldcg(src + i2);
        }
        __syncthreads();
    }
    if (tid < 128) g_c[dir][j2 * 32 + b2] = cst;
}

// ---------------------------------------------------------------------------
// Decoder: 128 CTAs x 2 units, K=512 ([h|x]) with half-restage trick.
//   layer0 X = [ h0 | x(=h1_prev) ]   sm_w0 = [ Whh0 | Wih0 ]
//   layer1 X = [ h0 | h1_prev    ]    sm_w1 = [ Wih1 | Whh1 ]
// ---------------------------------------------------------------------------
#define DEC_SMEM (8*513*2 + 512*34 + 256*17)

__device__ __forceinline__ void dec_stage_half(ull* d, const float* src, int half) {
    const ull* s = (const ull*)src;
    const int base = half * 4096;
#pragma unroll
    for (int r = 0; r < 16; r++) {
        int i2 = r * 256 + threadIdx.x;             // 0..4095
        d[((base + i2) >> 4) * 17 + (i2 & 15)] = __ldcg(s + i2);
    }
}

__global__ void __launch_bounds__(256) dec_kernel(const float* __restrict__ Wih0,
                                                  const float* __restrict__ Whh0,
                                                  const float* __restrict__ b0,
                                                  const float* __restrict__ Wih1,
                                                  const float* __restrict__ Whh1,
                                                  const float* __restrict__ b1,
                                                  const float* __restrict__ linW) {
    extern __shared__ float sm[];
    float* sm_w0 = sm;                   // 8*513
    float* sm_w1 = sm + 4104;            // 8*513
    float* sm_x  = sm + 8208;            // 512*34 (8-byte aligned)
    float* sm_red = sm + 8208 + 17408;   // 256*17

    const int tid = threadIdx.x, cta = blockIdx.x, j0 = cta << 1;

    for (int idx = tid; idx < 8 * 512; idx += 256) {
        int lr = idx >> 9, k = idx & 511, g = lr >> 1, uu = lr & 1;
        size_t grow = (size_t)(g * 256 + j0 + uu) * 256;
        sm_w0[lr * 513 + k] = (k < 256) ? Whh0[grow + k] : Wih0[grow + k - 256];
        sm_w1[lr * 513 + k] = (k < 256) ? Wih1[grow + k] : Whh1[grow + k - 256];
    }

    const int bq = tid & 3, rgq = (tid >> 2) & 3, kc = tid >> 4;
    const int u2 = tid >> 5, b2 = tid & 31, j2 = j0 + u2;
    float b0v[4]={0,0,0,0}, b1v[4]={0,0,0,0}, lwv[3]={0,0,0}, c0=0.f, c1=0.f;
    if (tid < 64) {
#pragma unroll
        for (int g = 0; g < 4; g++) { b0v[g] = b0[g*256+j2]; b1v[g] = b1[g*256+j2]; }
#pragma unroll
        for (int v = 0; v < 3; v++) lwv[v] = linW[v * 256 + j2];
        c0 = __ldcg(&g_c[0][j2 * 32 + b2]);
        c1 = __ldcg(&g_c[1][j2 * 32 + b2]);
    }

    const ull* X2 = (const ull*)sm_x;
    ull* X2w = (ull*)sm_x;

    // init: lower = hf (h0 state), upper = x_0 = 0
    dec_stage_half(X2w, g_h[0][0], 0);
#pragma unroll
    for (int r = 0; r < 16; r++) {
        int i2 = r * 256 + tid;
        X2w[((4096 + i2) >> 4) * 17 + (i2 & 15)] = 0ull;
    }
    __syncthreads();

    for (int t = 0; t < 64; t++) {
        for (int layer = 0; layer < 2; layer++) {
            const float* Wl = layer ? sm_w1 : sm_w0;
            ull acc[2][4];
#pragma unroll
            for (int r = 0; r < 2; r++)
#pragma unroll
                for (int p = 0; p < 4; p++) acc[r][p] = 0ull;
#pragma unroll 8
            for (int i = 0; i < 32; i++) {
                int k = kc + (i << 4);
                ull wp0 = pk2(Wl[(rgq*2+0)*513+k], Wl[(rgq*2+0)*513+k]);
                ull wp1 = pk2(Wl[(rgq*2+1)*513+k], Wl[(rgq*2+1)*513+k]);
                const ull* hb = X2 + k * 17 + bq * 4;
                ull h0 = hb[0], h1 = hb[1], h2 = hb[2], h3 = hb[3];
                ffma2(acc[0][0],wp0,h0); ffma2(acc[0][1],wp0,h1);
                ffma2(acc[0][2],wp0,h2); ffma2(acc[0][3],wp0,h3);
                ffma2(acc[1][0],wp1,h0); ffma2(acc[1][1],wp1,h1);
                ffma2(acc[1][2],wp1,h2); ffma2(acc[1][3],wp1,h3);
            }
            __syncthreads();
            {
                float* mr_ = sm_red + tid * 17;
#pragma unroll
                for (int r = 0; r < 2; r++)
#pragma unroll
                    for (int p = 0; p < 4; p++) {
                        float2 v = upk2(acc[r][p]);
                        mr_[r*8 + p*2] = v.x; mr_[r*8 + p*2 + 1] = v.y;
                    }
            }
            __syncthreads();

            if (tid < 64) {
                float s4[4];
#pragma unroll
                for (int g = 0; g < 4; g++) {
                    float a = layer ? b1v[g] : b0v[g];
#pragma unroll
                    for (int q = 0; q < 16; q++)
                        a += sm_red[((b2>>3) + g*4 + q*16)*17 + u2*8 + (b2&7)];
                    s4[g] = a;
                }
                float iv = sigf(s4[0]), fv = sigf(s4[1]);
                float gv = tanhf(s4[2]), ov = sigf(s4[3]);
                if (layer == 0) {
                    c0 = fv * c0 + iv * gv;
                    g_dh0[j2 * 32 + b2] = ov * tanhf(c0);
                } else {
                    c1 = fv * c1 + iv * gv;
                    float h = ov * tanhf(c1);
                    g_dh1[j2 * 32 + b2] = h;
#pragma unroll
                    for (int v = 0; v < 3; v++)
                        g_part[((size_t)t * 256 + (cta*2 + u2)) * 96 + b2*3 + v] = lwv[v] * h;
                }
            }

            barrier_sync(g_ctr_dec + t * 2 + layer, 128);

            if (layer == 0) {
                dec_stage_half(X2w, g_dh0, 0);             // lower <- h0_t
                if (t == 0) dec_stage_half(X2w, g_h[1][0], 1);  // upper <- hb
                __syncthreads();
            } else if (t < 63) {
                dec_stage_half(X2w, g_dh1, 1);             // upper <- h1_t
                __syncthreads();
            }
        }
    }
}

__global__ void reduce_y(const float* __restrict__ lin_b, float* __restrict__ out) {
    int t = blockIdx.x, o = threadIdx.x;   // o = b*3+v, 96 threads
    const float* p = g_part + (size_t)t * 256 * 96 + o;
    float a0 = 0.f, a1 = 0.f, a2 = 0.f, a3 = 0.f;
#pragma unroll 4
    for (int s = 0; s < 256; s += 4) {
        a0 += p[(size_t)(s + 0) * 96]; a1 += p[(size_t)(s + 1) * 96];
        a2 += p[(size_t)(s + 2) * 96]; a3 += p[(size_t)(s + 3) * 96];
    }
    out[t * 96 + o] = lin_b[o % 3] + ((a0 + a1) + (a2 + a3));
}

// ---------------------------------------------------------------------------
extern "C" void kernel_launch(void* const* d_in, const int* in_sizes, int n_in,
                              void* d_out, int out_size) {
    (void)in_sizes; (void)n_in; (void)out_size;
    const float* X     = (const float*)d_in[0];
    const float* eWihF = (const float*)d_in[1];
    const float* eWhhF = (const float*)d_in[2];
    const float* ebF   = (const float*)d_in[3];
    const float* eWihB = (const float*)d_in[4];
    const float* eWhhB = (const float*)d_in[5];
    const float* ebB   = (const float*)d_in[6];
    const float* dWih0 = (const float*)d_in[7];
    const float* dWhh0 = (const float*)d_in[8];
    const float* db0   = (const float*)d_in[9];
    const float* dWih1 = (const float*)d_in[10];
    const float* dWhh1 = (const float*)d_in[11];
    const float* db1   = (const float*)d_in[12];
    const float* linW  = (const float*)d_in[13];
    const float* linb  = (const float*)d_in[14];
    float* out = (float*)d_out;

    cudaFuncSetAttribute(enc_kernel, cudaFuncAttributeMaxDynamicSharedMemorySize,
                         ENC_SMEM * 4);
    cudaFuncSetAttribute(dec_kernel, cudaFuncAttributeMaxDynamicSharedMemorySize,
                         DEC_SMEM * 4);

    init_kernel<<<1, 1024>>>();
    gemm_pre<<<dim3(8, 128, 2), 256>>>(X, eWihF, eWihB);
    enc_kernel<<<dim3(64, 2), 256, ENC_SMEM * 4>>>(eWhhF, ebF, eWhhB, ebB);
    dec_kernel<<<128, 256, DEC_SMEM * 4>>>(dWih0, dWhh0, db0, dWih1, dWhh1, db1, linW);
    reduce_y<<<64, 96>>>(linb, out);
}